// round 15
// baseline (speedup 1.0000x reference)
#include <cuda_runtime.h>
#include <cuda_fp16.h>
#include <mma.h>
#include <cstdint>
#include <cstddef>
using namespace nvcuda;

#define NNODES 55296
#define NEDGES 221184
#define N32 (NNODES * 32)
#define NW 13824  // warps in h0 node pass (1728 blocks x 8)

// ------------------------- device scratch -----------------------------------
__device__ __align__(256) float g_h[2 * N32];
__device__ __align__(256) float g_agg[2 * N32];
__device__ __align__(256) __half g_tA[(size_t)NEDGES * 64];   // [e][64]: t|1|0pad
__device__ __align__(256) __half g_Bt2[48 * 1024];            // [k][j]: ew2'|eb2'|0
__device__ __align__(256) __half g_GB[128 * 128];             // fused GRU B matrix
__device__ __align__(256) __half g_We[(size_t)NEDGES * 1024]; // [e][j] j=(q,o,hl)

__device__ __forceinline__ float frcp(float x) {
    float r;
    asm("rcp.approx.f32 %0, %1;" : "=f"(r) : "f"(x));
    return r;
}
__device__ __forceinline__ float fsig(float x) { return frcp(1.f + __expf(-x)); }
__device__ __forceinline__ float ftanh(float x) {
    return 1.f - 2.f * frcp(1.f + __expf(2.f * x));
}
__device__ __forceinline__ uint64_t mkpol_ef() {
    uint64_t p;
    asm("createpolicy.fractional.L2::evict_first.b64 %0;" : "=l"(p));
    return p;
}
__device__ __forceinline__ uint4 ld_ef(const void* gp, uint64_t pol) {
    uint4 v;
    asm volatile("ld.global.nc.L2::cache_hint.v4.u32 {%0,%1,%2,%3}, [%4], %5;"
                 : "=r"(v.x), "=r"(v.y), "=r"(v.z), "=r"(v.w)
                 : "l"(gp), "l"(pol));
    return v;
}

// ---- launch 0: weight prep: B't2 [48][1024] + fused GRU B [128][128] --------
__global__ __launch_bounds__(256) void pre1_kernel(const float* __restrict__ ew2,
                                                   const float* __restrict__ eb2,
                                                   const float* __restrict__ wih,
                                                   const float* __restrict__ whh) {
    int b = blockIdx.x, tid = threadIdx.x;
    if (b < 192) {               // B't2: col j = q*256+o*8+hl ; rows: ew2|eb2|0
        int i = b * 256 + tid;
        int k = i >> 10, j = i & 1023;
        int h = ((j >> 8) << 3) + (j & 7), o = (j >> 3) & 31;
        float val = (k < 32) ? ew2[k * 1024 + h * 32 + o]
                             : (k == 32 ? eb2[h * 32 + o] : 0.f);
        g_Bt2[i] = __float2half(val);
    } else {                     // fused GRU B [128][128]
        int i = (b - 192) * 256 + tid;
        int k = i >> 7, j = i & 127;
        int h = k & 31, sect = j >> 5, jj = j & 31;
        float val;
        if (k < 64)
            val = (sect == 3) ? 0.f : wih[(sect * 32 + jj) * 32 + h];
        else
            val = (sect == 2) ? 0.f
                              : whh[((sect == 3 ? 2 : sect) * 32 + jj) * 32 + h];
        g_GB[i] = __float2half(val);
    }
}

// ---- launch 1: t = relu(rel@ew1+eb1) -> A' [e][64] = [t|1|0] ----------------
__global__ __launch_bounds__(256) void pre2_kernel(const float4* __restrict__ rel4,
                                                   const float* __restrict__ ew1,
                                                   const float* __restrict__ eb1) {
    int g = blockIdx.x * 256 + threadIdx.x;
    int e = g >> 6, k = g & 63;
    __half out;
    if (k < 32) {
        float4 r = rel4[e];
        float v = eb1[k] + r.x * ew1[k] + r.y * ew1[32 + k] +
                  r.z * ew1[64 + k] + r.w * ew1[96 + k];
        out = __float2half(fmaxf(v, 0.f));
    } else {
        out = __float2half(k == 32 ? 1.f : 0.f);
    }
    g_tA[(size_t)e * 64 + k] = out;
}

// ---- launch 2: h0 projection + zero g_agg (8 nodes per warp) ----------------
__global__ __launch_bounds__(256) void pre3_kernel(const float* __restrict__ x,
                                                   const float* __restrict__ pw1,
                                                   const float* __restrict__ pb1,
                                                   const float* __restrict__ pw2,
                                                   const float* __restrict__ pb2) {
    __shared__ float sW1[1024], sW2[1024];
    int tid = threadIdx.x, lane = tid & 31;
#pragma unroll
    for (int i = 0; i < 8; i++)
        g_agg[blockIdx.x * 256 + tid + i * 442368] = 0.f;
    for (int i = tid; i < 1024; i += 256) { sW1[i] = pw1[i]; sW2[i] = pw2[i]; }
    __syncthreads();
    int wbase = blockIdx.x * 8 + (tid >> 5);
#pragma unroll 1
    for (int it = 0; it < 8; it++) {
        int gw = wbase + it * NW;
        float xr = x[(size_t)gw * 32 + lane];
        float t1 = pb1[lane];
#pragma unroll
        for (int h = 0; h < 32; h++)
            t1 = fmaf(__shfl_sync(0xffffffffu, xr, h), sW1[h * 32 + lane], t1);
        t1 = fmaxf(t1, 0.f);
        float o = pb2[lane];
#pragma unroll
        for (int h = 0; h < 32; h++)
            o = fmaf(__shfl_sync(0xffffffffu, t1, h), sW2[h * 32 + lane], o);
        g_h[(size_t)gw * 32 + lane] = o;
    }
}

// ---- launch 3 (PROFILED): We GEMM, 2 m-tiles/warp -> B-load:mma = 0.5 -------
#define W2TOT 99072   // B smem: 48*1032*2

__global__ __launch_bounds__(256, 2) void we_wmma_kernel() {
    extern __shared__ char sm[];
    __half* sB = (__half*)sm;
    int tid = threadIdx.x, wid = tid >> 5;

    // B: 48 x 1024 halves -> smem stride 1032 (24 uint4 iters)
    const uint4* gb = (const uint4*)(const void*)g_Bt2;
#pragma unroll
    for (int r = 0; r < 24; r++) {
        int i = tid + r * 256, row = i >> 7, c = i & 127;
        *(uint4*)(sB + row * 1032 + c * 8) = gb[i];
    }
    __syncthreads();

    // warp owns 32 edges = 2 m-tiles; A fragments hoisted from global
    int e0 = blockIdx.x * 256 + wid * 32;
    wmma::fragment<wmma::matrix_a, 16, 16, 16, __half, wmma::row_major> af[2][3];
#pragma unroll
    for (int m = 0; m < 2; m++)
#pragma unroll
        for (int k = 0; k < 3; k++)
            wmma::load_matrix_sync(af[m][k],
                                   (const __half*)g_tA +
                                       (size_t)(e0 + m * 16) * 64 + k * 16,
                                   64);

    __half* gout = (__half*)(void*)g_We + (size_t)e0 * 1024;
#pragma unroll 1
    for (int nt = 0; nt < 16; nt++) {
#pragma unroll
        for (int f = 0; f < 4; f++) {
            wmma::fragment<wmma::accumulator, 16, 16, 16, float> acc0, acc1;
            wmma::fill_fragment(acc0, 0.f);
            wmma::fill_fragment(acc1, 0.f);
#pragma unroll
            for (int k = 0; k < 3; k++) {
                wmma::fragment<wmma::matrix_b, 16, 16, 16, __half, wmma::row_major> bf;
                wmma::load_matrix_sync(bf, sB + (k * 16) * 1032 + nt * 64 + f * 16,
                                       1032);
                wmma::mma_sync(acc0, af[0][k], bf, acc0);
                wmma::mma_sync(acc1, af[1][k], bf, acc1);
            }
            wmma::fragment<wmma::accumulator, 16, 16, 16, __half> h0, h1;
#pragma unroll
            for (int i = 0; i < acc0.num_elements; i++) {
                h0.x[i] = __float2half(acc0.x[i]);
                h1.x[i] = __float2half(acc1.x[i]);
            }
            wmma::store_matrix_sync(gout + nt * 64 + f * 16, h0, 1024,
                                    wmma::mem_row_major);
            wmma::store_matrix_sync(gout + 16 * 1024 + nt * 64 + f * 16, h1, 1024,
                                    wmma::mem_row_major);
        }
    }
}

// ---- msg + scatter, 2 edges per warp (DRAM-bound, ~roofline, unchanged) -----
__global__ __launch_bounds__(256) void msg_kernel(const int* __restrict__ src,
                                                  const int* __restrict__ dst) {
    __shared__ __align__(16) float ns[8][4][32];
    const int w = threadIdx.x >> 5, lane = threadIdx.x & 31;
    const int e0 = blockIdx.x * 16 + w * 2;
    uint64_t pol = mkpol_ef();
    int s0 = __ldg(&src[e0]), s1 = __ldg(&src[e0 + 1]);
    int d0 = __ldg(&dst[e0]), d1 = __ldg(&dst[e0 + 1]);
    ns[w][0][lane] = g_h[(size_t)s0 * 32 + lane];
    ns[w][1][lane] = g_h[N32 + (size_t)s0 * 32 + lane];
    ns[w][2][lane] = g_h[(size_t)s1 * 32 + lane];
    ns[w][3][lane] = g_h[N32 + (size_t)s1 * 32 + lane];
    uint4 q[8];
#pragma unroll
    for (int ee = 0; ee < 2; ee++)
#pragma unroll
        for (int qi = 0; qi < 4; qi++)
            q[ee * 4 + qi] = ld_ef((const char*)(const void*)g_We +
                                       (size_t)(e0 + ee) * 2048 + qi * 512 +
                                       lane * 16,
                                   pol);
    __syncwarp();
    float acc[4] = {0.f, 0.f, 0.f, 0.f};
#pragma unroll
    for (int ee = 0; ee < 2; ee++) {
#pragma unroll
        for (int qi = 0; qi < 4; qi++) {
            uint32_t w4[4] = {q[ee * 4 + qi].x, q[ee * 4 + qi].y,
                              q[ee * 4 + qi].z, q[ee * 4 + qi].w};
#pragma unroll
            for (int u = 0; u < 4; u++) {
                float2 wf = __half22float2(*(__half2*)&w4[u]);
                int h = qi * 8 + 2 * u;
                float2 p0 = *(const float2*)&ns[w][ee * 2][h];
                float2 p1 = *(const float2*)&ns[w][ee * 2 + 1][h];
                acc[ee * 2] += p0.x * wf.x + p0.y * wf.y;
                acc[ee * 2 + 1] += p1.x * wf.x + p1.y * wf.y;
            }
        }
    }
#pragma unroll
    for (int ee = 0; ee < 2; ee++) {
        int d = ee ? d1 : d0;
        float a0 = acc[ee * 2], a1 = acc[ee * 2 + 1];
        float u = __shfl_down_sync(0xffffffffu, a0, 1);
        float v = __shfl_up_sync(0xffffffffu, a1, 1);
        if (!(lane & 1))
            asm volatile("red.global.add.v2.f32 [%0], {%1,%2};"
                         :: "l"(&g_agg[(size_t)d * 32 + lane]), "f"(a0), "f"(u)
                         : "memory");
        else
            asm volatile("red.global.add.v2.f32 [%0], {%1,%2};"
                         :: "l"(&g_agg[N32 + (size_t)d * 32 + lane - 1]), "f"(v),
                            "f"(a1)
                         : "memory");
    }
}

// ---- fused single-GEMM GRU, prebuilt B, 2 CTA/SM (609us-best version) -------
#define GA 0          // 96*136*2  = 26112
#define GB 26112      // 128*136*2 = 34816
#define GC 60928      // 96*132*4  = 50688
#define GBI 111616    // 192*4     = 768
#define GTOT 112384

__global__ __launch_bounds__(256, 2) void gru_kernel(const float* __restrict__ convb,
                                                     const float* __restrict__ bih,
                                                     const float* __restrict__ bhh,
                                                     float* __restrict__ outp) {
    extern __shared__ char sm[];
    __half* sA = (__half*)(sm + GA);
    __half* sB = (__half*)(sm + GB);
    float* sC = (float*)(sm + GC);
    float* sBI = (float*)(sm + GBI);
    int tid = threadIdx.x, wid = tid >> 5;
    size_t base = (size_t)blockIdx.x * 3072;

    // stage A: relu(agg+cb) hi/lo and hidden hi/lo; reset agg
#pragma unroll
    for (int i = 0; i < 12; i++) {
        int v = tid + i * 256, row = v >> 5, col = v & 31;
        float nf = fmaxf(g_agg[base + v] + convb[col], 0.f);
        g_agg[base + v] = 0.f;
        __half nh = __float2half(nf);
        sA[row * 136 + col] = nh;
        sA[row * 136 + 32 + col] = __float2half(nf - __half2float(nh));
        float hf = g_h[base + v];
        __half hh = __float2half(hf);
        sA[row * 136 + 64 + col] = hh;
        sA[row * 136 + 96 + col] = __float2half(hf - __half2float(hh));
    }
    // stage B: vectorized copy of prebuilt fused matrix
    {
        const uint4* gB4 = (const uint4*)(const void*)g_GB;
#pragma unroll
        for (int r = 0; r < 8; r++) {
            int v = tid + r * 256, row = v >> 4, c = v & 15;
            *(uint4*)(sB + row * 136 + c * 8) = gB4[v];
        }
    }
    if (tid < 96) { sBI[tid] = bih[tid]; sBI[96 + tid] = bhh[tid]; }
    __syncthreads();

    // GEMM [96x128]@[128x128]; warp owns cols [wid*16,+16); m unrolled x2
    wmma::fragment<wmma::matrix_b, 16, 16, 16, __half, wmma::row_major> bf[8];
#pragma unroll
    for (int k = 0; k < 8; k++)
        wmma::load_matrix_sync(bf[k], sB + (k * 16) * 136 + wid * 16, 136);
#pragma unroll 1
    for (int mp = 0; mp < 3; mp++) {
        wmma::fragment<wmma::accumulator, 16, 16, 16, float> acc0, acc1;
        wmma::fill_fragment(acc0, 0.f);
        wmma::fill_fragment(acc1, 0.f);
#pragma unroll
        for (int k = 0; k < 8; k++) {
            wmma::fragment<wmma::matrix_a, 16, 16, 16, __half, wmma::row_major> a0,
                a1;
            wmma::load_matrix_sync(a0, sA + (mp * 32) * 136 + k * 16, 136);
            wmma::load_matrix_sync(a1, sA + (mp * 32 + 16) * 136 + k * 16, 136);
            wmma::mma_sync(acc0, a0, bf[k], acc0);
            wmma::mma_sync(acc1, a1, bf[k], acc1);
        }
        wmma::store_matrix_sync(sC + (mp * 32) * 132 + wid * 16, acc0, 132,
                                wmma::mem_row_major);
        wmma::store_matrix_sync(sC + (mp * 32 + 16) * 132 + wid * 16, acc1, 132,
                                wmma::mem_row_major);
    }
    __syncthreads();

    // epilogue: gates + state update (hid recovered exactly from hi+lo)
#pragma unroll
    for (int i = 0; i < 12; i++) {
        int v = tid + i * 256, row = v >> 5, j = v & 31;
        const float* c = sC + row * 132;
        float r = fsig(c[j] + sBI[j] + sBI[96 + j]);
        float z = fsig(c[32 + j] + sBI[32 + j] + sBI[128 + j]);
        float n = ftanh(c[64 + j] + sBI[64 + j] + r * (c[96 + j] + sBI[160 + j]));
        float hid = __half2float(sA[row * 136 + 64 + j]) +
                    __half2float(sA[row * 136 + 96 + j]);
        float hn = (1.f - z) * n + z * hid;
        if (outp) outp[base + v] = hn;
        else g_h[base + v] = hn;
    }
}

// ------------------------- launch -------------------------------------------
extern "C" void kernel_launch(void* const* d_in, const int* in_sizes, int n_in,
                              void* d_out, int out_size) {
    const float* x     = (const float*)d_in[0];
    const float* rel   = (const float*)d_in[1];
    const float* pw1   = (const float*)d_in[2];
    const float* pb1   = (const float*)d_in[3];
    const float* pw2   = (const float*)d_in[4];
    const float* pb2   = (const float*)d_in[5];
    const float* ew1   = (const float*)d_in[6];
    const float* eb1   = (const float*)d_in[7];
    const float* ew2   = (const float*)d_in[8];
    const float* eb2   = (const float*)d_in[9];
    const float* convb = (const float*)d_in[10];
    const float* wih   = (const float*)d_in[11];
    const float* whh   = (const float*)d_in[12];
    const float* bih   = (const float*)d_in[13];
    const float* bhh   = (const float*)d_in[14];
    const int*   src   = (const int*)d_in[15];
    const int*   dst   = (const int*)d_in[16];
    float* out = (float*)d_out;

    cudaFuncSetAttribute(we_wmma_kernel,
                         cudaFuncAttributeMaxDynamicSharedMemorySize, W2TOT);
    cudaFuncSetAttribute(gru_kernel,
                         cudaFuncAttributeMaxDynamicSharedMemorySize, GTOT);
    pre1_kernel<<<256, 256>>>(ew2, eb2, wih, whh);
    pre2_kernel<<<(NEDGES * 64) / 256, 256>>>((const float4*)rel, ew1, eb1);
    pre3_kernel<<<1728, 256>>>(x, pw1, pb1, pw2, pb2);
    we_wmma_kernel<<<NEDGES / 256, 256, W2TOT>>>();
    for (int step = 0; step < 3; step++) {
        msg_kernel<<<NEDGES / 16, 256>>>(src, dst);
        gru_kernel<<<1152, 256, GTOT>>>(convb, bih, bhh,
                                        step == 2 ? out : nullptr);
    }
}

// round 16
// speedup vs baseline: 1.0547x; 1.0547x over previous
#include <cuda_runtime.h>
#include <cuda_fp16.h>
#include <mma.h>
#include <cstdint>
#include <cstddef>
using namespace nvcuda;

#define NNODES 55296
#define NEDGES 221184
#define N32 (NNODES * 32)
#define NW 13824  // warps in h0 node pass (1728 blocks x 8)

// ------------------------- device scratch -----------------------------------
__device__ __align__(256) float g_h[2 * N32];
__device__ __align__(256) float g_agg[2 * N32];
__device__ __align__(256) __half g_tA[(size_t)NEDGES * 64];   // [e][64]: t|1|0pad
__device__ __align__(256) __half g_Bt2[48 * 1024];            // [k][j]: ew2'|eb2'|0
__device__ __align__(256) __half g_GB[128 * 128];             // fused GRU B matrix
__device__ __align__(256) __half g_We[(size_t)NEDGES * 1024]; // [e][j] j=(q,o,hl)

__device__ __forceinline__ float frcp(float x) {
    float r;
    asm("rcp.approx.f32 %0, %1;" : "=f"(r) : "f"(x));
    return r;
}
__device__ __forceinline__ float fsig(float x) { return frcp(1.f + __expf(-x)); }
__device__ __forceinline__ float ftanh(float x) {
    return 1.f - 2.f * frcp(1.f + __expf(2.f * x));
}
__device__ __forceinline__ uint64_t mkpol_ef() {
    uint64_t p;
    asm("createpolicy.fractional.L2::evict_first.b64 %0;" : "=l"(p));
    return p;
}
__device__ __forceinline__ uint4 ld_ef(const void* gp, uint64_t pol) {
    uint4 v;
    asm volatile("ld.global.nc.L2::cache_hint.v4.u32 {%0,%1,%2,%3}, [%4], %5;"
                 : "=r"(v.x), "=r"(v.y), "=r"(v.z), "=r"(v.w)
                 : "l"(gp), "l"(pol));
    return v;
}

// ---- launch 0: weight prep: B't2 [48][1024] + fused GRU B [128][128] --------
__global__ __launch_bounds__(256) void pre1_kernel(const float* __restrict__ ew2,
                                                   const float* __restrict__ eb2,
                                                   const float* __restrict__ wih,
                                                   const float* __restrict__ whh) {
    int b = blockIdx.x, tid = threadIdx.x;
    if (b < 192) {               // B't2: col j = q*256+o*8+hl ; rows: ew2|eb2|0
        int i = b * 256 + tid;
        int k = i >> 10, j = i & 1023;
        int h = ((j >> 8) << 3) + (j & 7), o = (j >> 3) & 31;
        float val = (k < 32) ? ew2[k * 1024 + h * 32 + o]
                             : (k == 32 ? eb2[h * 32 + o] : 0.f);
        g_Bt2[i] = __float2half(val);
    } else {                     // fused GRU B [128][128]
        int i = (b - 192) * 256 + tid;
        int k = i >> 7, j = i & 127;
        int h = k & 31, sect = j >> 5, jj = j & 31;
        float val;
        if (k < 64)
            val = (sect == 3) ? 0.f : wih[(sect * 32 + jj) * 32 + h];
        else
            val = (sect == 2) ? 0.f
                              : whh[((sect == 3 ? 2 : sect) * 32 + jj) * 32 + h];
        g_GB[i] = __float2half(val);
    }
}

// ---- launch 1: t = relu(rel@ew1+eb1) -> A' [e][64] = [t|1|0], 4 halves/thr --
__global__ __launch_bounds__(256) void pre2_kernel(const float4* __restrict__ rel4,
                                                   const float* __restrict__ ew1,
                                                   const float* __restrict__ eb1) {
    int g = blockIdx.x * 256 + threadIdx.x;
    int e = g >> 4, q = g & 15;  // quad of 4 halves
    __half2 lo, hi;
    if (q < 8) {
        float4 r = rel4[e];
        float v[4];
#pragma unroll
        for (int u = 0; u < 4; u++) {
            int k = q * 4 + u;
            float t = eb1[k] + r.x * ew1[k] + r.y * ew1[32 + k] +
                      r.z * ew1[64 + k] + r.w * ew1[96 + k];
            v[u] = fmaxf(t, 0.f);
        }
        lo = __floats2half2_rn(v[0], v[1]);
        hi = __floats2half2_rn(v[2], v[3]);
    } else if (q == 8) {
        lo = __floats2half2_rn(1.f, 0.f);
        hi = __floats2half2_rn(0.f, 0.f);
    } else {
        lo = __floats2half2_rn(0.f, 0.f);
        hi = lo;
    }
    uint2 pk;
    pk.x = *(uint32_t*)&lo;
    pk.y = *(uint32_t*)&hi;
    *(uint2*)((__half*)g_tA + (size_t)e * 64 + q * 4) = pk;
}

// ---- launch 2: h0 projection + zero g_agg (8 nodes per warp) ----------------
__global__ __launch_bounds__(256) void pre3_kernel(const float* __restrict__ x,
                                                   const float* __restrict__ pw1,
                                                   const float* __restrict__ pb1,
                                                   const float* __restrict__ pw2,
                                                   const float* __restrict__ pb2) {
    __shared__ float sW1[1024], sW2[1024];
    int tid = threadIdx.x, lane = tid & 31;
#pragma unroll
    for (int i = 0; i < 8; i++)
        g_agg[blockIdx.x * 256 + tid + i * 442368] = 0.f;
    for (int i = tid; i < 1024; i += 256) { sW1[i] = pw1[i]; sW2[i] = pw2[i]; }
    __syncthreads();
    int wbase = blockIdx.x * 8 + (tid >> 5);
#pragma unroll 1
    for (int it = 0; it < 8; it++) {
        int gw = wbase + it * NW;
        float xr = x[(size_t)gw * 32 + lane];
        float t1 = pb1[lane];
#pragma unroll
        for (int h = 0; h < 32; h++)
            t1 = fmaf(__shfl_sync(0xffffffffu, xr, h), sW1[h * 32 + lane], t1);
        t1 = fmaxf(t1, 0.f);
        float o = pb2[lane];
#pragma unroll
        for (int h = 0; h < 32; h++)
            o = fmaf(__shfl_sync(0xffffffffu, t1, h), sW2[h * 32 + lane], o);
        g_h[(size_t)gw * 32 + lane] = o;
    }
}

// ---- launch 3 (PROFILED): We GEMM, col-split x2, slim regs, 3 CTA/SM --------
#define W3TOT 49920   // B smem: 48*520*2

__global__ __launch_bounds__(256, 3) void we_wmma_kernel() {
    extern __shared__ char sm[];
    __half* sB = (__half*)sm;
    int tid = threadIdx.x, wid = tid >> 5;
    int eg = blockIdx.x >> 1;          // edge group 0..1727
    int ch2 = (blockIdx.x & 1) * 512;  // column half offset

    // B half: 48 rows x 512 cols -> smem stride 520 (12 uint4 iters)
    const uint4* gb = (const uint4*)(const void*)g_Bt2;
#pragma unroll
    for (int r = 0; r < 12; r++) {
        int i = tid + r * 256, row = i >> 6, c = i & 63;
        *(uint4*)(sB + row * 520 + c * 8) = gb[row * 128 + (ch2 >> 3) + c];
    }
    __syncthreads();

    // warp owns 16 edges; A fragments hoisted from global
    int e0 = eg * 128 + wid * 16;
    wmma::fragment<wmma::matrix_a, 16, 16, 16, __half, wmma::row_major> af[3];
#pragma unroll
    for (int k = 0; k < 3; k++)
        wmma::load_matrix_sync(af[k],
                               (const __half*)g_tA + (size_t)e0 * 64 + k * 16, 64);

    __half* gout = (__half*)(void*)g_We + (size_t)e0 * 1024 + ch2;
#pragma unroll 1
    for (int nt = 0; nt < 8; nt++) {
#pragma unroll
        for (int f = 0; f < 4; f++) {
            wmma::fragment<wmma::accumulator, 16, 16, 16, float> acc;
            wmma::fill_fragment(acc, 0.f);
#pragma unroll
            for (int k = 0; k < 3; k++) {
                wmma::fragment<wmma::matrix_b, 16, 16, 16, __half, wmma::row_major> bf;
                wmma::load_matrix_sync(bf, sB + (k * 16) * 520 + nt * 64 + f * 16,
                                       520);
                wmma::mma_sync(acc, af[k], bf, acc);
            }
            wmma::fragment<wmma::accumulator, 16, 16, 16, __half> hacc;
#pragma unroll
            for (int i = 0; i < acc.num_elements; i++)
                hacc.x[i] = __float2half(acc.x[i]);
            wmma::store_matrix_sync(gout + nt * 64 + f * 16, hacc, 1024,
                                    wmma::mem_row_major);
        }
    }
}

// ---- msg + scatter, 2 edges per warp (DRAM-bound, ~roofline, unchanged) -----
__global__ __launch_bounds__(256) void msg_kernel(const int* __restrict__ src,
                                                  const int* __restrict__ dst) {
    __shared__ __align__(16) float ns[8][4][32];
    const int w = threadIdx.x >> 5, lane = threadIdx.x & 31;
    const int e0 = blockIdx.x * 16 + w * 2;
    uint64_t pol = mkpol_ef();
    int s0 = __ldg(&src[e0]), s1 = __ldg(&src[e0 + 1]);
    int d0 = __ldg(&dst[e0]), d1 = __ldg(&dst[e0 + 1]);
    ns[w][0][lane] = g_h[(size_t)s0 * 32 + lane];
    ns[w][1][lane] = g_h[N32 + (size_t)s0 * 32 + lane];
    ns[w][2][lane] = g_h[(size_t)s1 * 32 + lane];
    ns[w][3][lane] = g_h[N32 + (size_t)s1 * 32 + lane];
    uint4 q[8];
#pragma unroll
    for (int ee = 0; ee < 2; ee++)
#pragma unroll
        for (int qi = 0; qi < 4; qi++)
            q[ee * 4 + qi] = ld_ef((const char*)(const void*)g_We +
                                       (size_t)(e0 + ee) * 2048 + qi * 512 +
                                       lane * 16,
                                   pol);
    __syncwarp();
    float acc[4] = {0.f, 0.f, 0.f, 0.f};
#pragma unroll
    for (int ee = 0; ee < 2; ee++) {
#pragma unroll
        for (int qi = 0; qi < 4; qi++) {
            uint32_t w4[4] = {q[ee * 4 + qi].x, q[ee * 4 + qi].y,
                              q[ee * 4 + qi].z, q[ee * 4 + qi].w};
#pragma unroll
            for (int u = 0; u < 4; u++) {
                float2 wf = __half22float2(*(__half2*)&w4[u]);
                int h = qi * 8 + 2 * u;
                float2 p0 = *(const float2*)&ns[w][ee * 2][h];
                float2 p1 = *(const float2*)&ns[w][ee * 2 + 1][h];
                acc[ee * 2] += p0.x * wf.x + p0.y * wf.y;
                acc[ee * 2 + 1] += p1.x * wf.x + p1.y * wf.y;
            }
        }
    }
#pragma unroll
    for (int ee = 0; ee < 2; ee++) {
        int d = ee ? d1 : d0;
        float a0 = acc[ee * 2], a1 = acc[ee * 2 + 1];
        float u = __shfl_down_sync(0xffffffffu, a0, 1);
        float v = __shfl_up_sync(0xffffffffu, a1, 1);
        if (!(lane & 1))
            asm volatile("red.global.add.v2.f32 [%0], {%1,%2};"
                         :: "l"(&g_agg[(size_t)d * 32 + lane]), "f"(a0), "f"(u)
                         : "memory");
        else
            asm volatile("red.global.add.v2.f32 [%0], {%1,%2};"
                         :: "l"(&g_agg[N32 + (size_t)d * 32 + lane - 1]), "f"(v),
                            "f"(a1)
                         : "memory");
    }
}

// ---- fused single-GEMM GRU, prebuilt B, 2 CTA/SM (609us-best version) -------
#define GA 0          // 96*136*2  = 26112
#define GB 26112      // 128*136*2 = 34816
#define GC 60928      // 96*132*4  = 50688
#define GBI 111616    // 192*4     = 768
#define GTOT 112384

__global__ __launch_bounds__(256, 2) void gru_kernel(const float* __restrict__ convb,
                                                     const float* __restrict__ bih,
                                                     const float* __restrict__ bhh,
                                                     float* __restrict__ outp) {
    extern __shared__ char sm[];
    __half* sA = (__half*)(sm + GA);
    __half* sB = (__half*)(sm + GB);
    float* sC = (float*)(sm + GC);
    float* sBI = (float*)(sm + GBI);
    int tid = threadIdx.x, wid = tid >> 5;
    size_t base = (size_t)blockIdx.x * 3072;

    // stage A: relu(agg+cb) hi/lo and hidden hi/lo; reset agg
#pragma unroll
    for (int i = 0; i < 12; i++) {
        int v = tid + i * 256, row = v >> 5, col = v & 31;
        float nf = fmaxf(g_agg[base + v] + convb[col], 0.f);
        g_agg[base + v] = 0.f;
        __half nh = __float2half(nf);
        sA[row * 136 + col] = nh;
        sA[row * 136 + 32 + col] = __float2half(nf - __half2float(nh));
        float hf = g_h[base + v];
        __half hh = __float2half(hf);
        sA[row * 136 + 64 + col] = hh;
        sA[row * 136 + 96 + col] = __float2half(hf - __half2float(hh));
    }
    // stage B: vectorized copy of prebuilt fused matrix
    {
        const uint4* gB4 = (const uint4*)(const void*)g_GB;
#pragma unroll
        for (int r = 0; r < 8; r++) {
            int v = tid + r * 256, row = v >> 4, c = v & 15;
            *(uint4*)(sB + row * 136 + c * 8) = gB4[v];
        }
    }
    if (tid < 96) { sBI[tid] = bih[tid]; sBI[96 + tid] = bhh[tid]; }
    __syncthreads();

    // GEMM [96x128]@[128x128]; warp owns cols [wid*16,+16); m unrolled x2
    wmma::fragment<wmma::matrix_b, 16, 16, 16, __half, wmma::row_major> bf[8];
#pragma unroll
    for (int k = 0; k < 8; k++)
        wmma::load_matrix_sync(bf[k], sB + (k * 16) * 136 + wid * 16, 136);
#pragma unroll 1
    for (int mp = 0; mp < 3; mp++) {
        wmma::fragment<wmma::accumulator, 16, 16, 16, float> acc0, acc1;
        wmma::fill_fragment(acc0, 0.f);
        wmma::fill_fragment(acc1, 0.f);
#pragma unroll
        for (int k = 0; k < 8; k++) {
            wmma::fragment<wmma::matrix_a, 16, 16, 16, __half, wmma::row_major> a0,
                a1;
            wmma::load_matrix_sync(a0, sA + (mp * 32) * 136 + k * 16, 136);
            wmma::load_matrix_sync(a1, sA + (mp * 32 + 16) * 136 + k * 16, 136);
            wmma::mma_sync(acc0, a0, bf[k], acc0);
            wmma::mma_sync(acc1, a1, bf[k], acc1);
        }
        wmma::store_matrix_sync(sC + (mp * 32) * 132 + wid * 16, acc0, 132,
                                wmma::mem_row_major);
        wmma::store_matrix_sync(sC + (mp * 32 + 16) * 132 + wid * 16, acc1, 132,
                                wmma::mem_row_major);
    }
    __syncthreads();

    // epilogue: gates + state update (hid recovered exactly from hi+lo)
#pragma unroll
    for (int i = 0; i < 12; i++) {
        int v = tid + i * 256, row = v >> 5, j = v & 31;
        const float* c = sC + row * 132;
        float r = fsig(c[j] + sBI[j] + sBI[96 + j]);
        float z = fsig(c[32 + j] + sBI[32 + j] + sBI[128 + j]);
        float n = ftanh(c[64 + j] + sBI[64 + j] + r * (c[96 + j] + sBI[160 + j]));
        float hid = __half2float(sA[row * 136 + 64 + j]) +
                    __half2float(sA[row * 136 + 96 + j]);
        float hn = (1.f - z) * n + z * hid;
        if (outp) outp[base + v] = hn;
        else g_h[base + v] = hn;
    }
}

// ------------------------- launch -------------------------------------------
extern "C" void kernel_launch(void* const* d_in, const int* in_sizes, int n_in,
                              void* d_out, int out_size) {
    const float* x     = (const float*)d_in[0];
    const float* rel   = (const float*)d_in[1];
    const float* pw1   = (const float*)d_in[2];
    const float* pb1   = (const float*)d_in[3];
    const float* pw2   = (const float*)d_in[4];
    const float* pb2   = (const float*)d_in[5];
    const float* ew1   = (const float*)d_in[6];
    const float* eb1   = (const float*)d_in[7];
    const float* ew2   = (const float*)d_in[8];
    const float* eb2   = (const float*)d_in[9];
    const float* convb = (const float*)d_in[10];
    const float* wih   = (const float*)d_in[11];
    const float* whh   = (const float*)d_in[12];
    const float* bih   = (const float*)d_in[13];
    const float* bhh   = (const float*)d_in[14];
    const int*   src   = (const int*)d_in[15];
    const int*   dst   = (const int*)d_in[16];
    float* out = (float*)d_out;

    cudaFuncSetAttribute(we_wmma_kernel,
                         cudaFuncAttributeMaxDynamicSharedMemorySize, W3TOT);
    cudaFuncSetAttribute(gru_kernel,
                         cudaFuncAttributeMaxDynamicSharedMemorySize, GTOT);
    pre1_kernel<<<256, 256>>>(ew2, eb2, wih, whh);
    pre2_kernel<<<(NEDGES * 16) / 256, 256>>>((const float4*)rel, ew1, eb1);
    pre3_kernel<<<1728, 256>>>(x, pw1, pb1, pw2, pb2);
    we_wmma_kernel<<<3456, 256, W3TOT>>>();
    for (int step = 0; step < 3; step++) {
        msg_kernel<<<NEDGES / 16, 256>>>(src, dst);
        gru_kernel<<<1152, 256, GTOT>>>(convb, bih, bhh,
                                        step == 2 ? out : nullptr);
    }
}